// round 11
// baseline (speedup 1.0000x reference)
#include <cuda_runtime.h>
#include <math.h>

#define BB   128
#define NS   128
#define NQ   512
#define DIN  256
#define DOUT 64

#define MU_N  ((long long)BB * NQ * DOUT)            // 4,194,304
#define SIG_N ((long long)BB * NQ * DOUT * DOUT)     // 134,217,728

// ---------------- scratch (floats) ----------------
#define OFF_SP     0LL
#define OFF_MPN    65536LL
#define OFF_SINV   81920LL
#define OFF_W      8470528LL
#define OFF_V      16859136LL
#define OFF_X      18956288LL
#define OFF_SC     21053440LL
#define OFF_RHS    23150592LL
#define OFF_T      25247744LL
#define OFF_M      27344896LL
#define OFF_SPREAD 29442048LL
#define BUF_TOTAL  29507584LL

__device__ float  g_buf[BUF_TOTAL];
__device__ double g_nll_acc;

// ======================================================================
// Batched SGEMM, 128x(BN) CTA tile, 256 threads, 8x(BN/16) reg tile,
// double-buffered shared memory.
// ======================================================================
template<int BM, int BN, int TA, int TB, bool SPREPI>
__global__ void __launch_bounds__(256, 2) gemm_k(
    int M, int N, int K,
    const float* __restrict__ A, int lda, long long sA,
    const float* __restrict__ B, int ldb, long long sB,
    const float* __restrict__ Dd, int ldd, long long sD,
    float alpha,
    float* __restrict__ C, int ldc, long long sC,
    float* __restrict__ spread)
{
    constexpr int TM  = BM / 16;
    constexpr int TN  = BN / 16;
    constexpr int LAS = BM + 4;
    constexpr int LBS = BN + 4;
    constexpr int NLA = (BM * 4) / 256;
    constexpr int NLB = (BN * 4) / 256;

    __shared__ float As[2][16][LAS];
    __shared__ float Bs[2][16][LBS];

    const int b  = blockIdx.z;
    const float* Ab = A + (long long)b * sA;
    const float* Bb = B + (long long)b * sB;

    const int m0 = blockIdx.y * BM;
    const int n0 = blockIdx.x * BN;
    const int tid = threadIdx.x;
    const int tx = tid & 15;
    const int ty = tid >> 4;

    float4 ra[NLA], rb[NLB];

    auto ldA = [&](int k0) {
        if constexpr (TA == 0) {
#pragma unroll
            for (int q = 0; q < NLA; q++) {
                int p = tid + q * 256;
                int m = p >> 2, kq = (p & 3) * 4;
                ra[q] = *(const float4*)(Ab + (long long)(m0 + m) * lda + k0 + kq);
            }
        } else {
#pragma unroll
            for (int q = 0; q < NLA; q++) {
                int p = tid + q * 256;
                int k = p / (BM / 4), mq = (p % (BM / 4)) * 4;
                ra[q] = *(const float4*)(Ab + (long long)(k0 + k) * lda + m0 + mq);
            }
        }
    };
    auto stA = [&](int s) {
        if constexpr (TA == 0) {
#pragma unroll
            for (int q = 0; q < NLA; q++) {
                int p = tid + q * 256;
                int m = p >> 2, kq = (p & 3) * 4;
                As[s][kq + 0][m] = ra[q].x; As[s][kq + 1][m] = ra[q].y;
                As[s][kq + 2][m] = ra[q].z; As[s][kq + 3][m] = ra[q].w;
            }
        } else {
#pragma unroll
            for (int q = 0; q < NLA; q++) {
                int p = tid + q * 256;
                int k = p / (BM / 4), mq = (p % (BM / 4)) * 4;
                *(float4*)&As[s][k][mq] = ra[q];
            }
        }
    };
    auto ldB = [&](int k0) {
        if constexpr (TB == 0) {
#pragma unroll
            for (int q = 0; q < NLB; q++) {
                int p = tid + q * 256;
                int k = p / (BN / 4), nq = (p % (BN / 4)) * 4;
                rb[q] = *(const float4*)(Bb + (long long)(k0 + k) * ldb + n0 + nq);
            }
        } else {
#pragma unroll
            for (int q = 0; q < NLB; q++) {
                int p = tid + q * 256;
                int n = p >> 2, kq = (p & 3) * 4;
                rb[q] = *(const float4*)(Bb + (long long)(n0 + n) * ldb + k0 + kq);
            }
        }
    };
    auto stB = [&](int s) {
        if constexpr (TB == 0) {
#pragma unroll
            for (int q = 0; q < NLB; q++) {
                int p = tid + q * 256;
                int k = p / (BN / 4), nq = (p % (BN / 4)) * 4;
                *(float4*)&Bs[s][k][nq] = rb[q];
            }
        } else {
#pragma unroll
            for (int q = 0; q < NLB; q++) {
                int p = tid + q * 256;
                int n = p >> 2, kq = (p & 3) * 4;
                Bs[s][kq + 0][n] = rb[q].x; Bs[s][kq + 1][n] = rb[q].y;
                Bs[s][kq + 2][n] = rb[q].z; Bs[s][kq + 3][n] = rb[q].w;
            }
        }
    };

    float acc[TM][TN];
#pragma unroll
    for (int i = 0; i < TM; i++)
#pragma unroll
        for (int j = 0; j < TN; j++) acc[i][j] = 0.f;

    ldA(0); ldB(0);
    stA(0); stB(0);
    __syncthreads();

    int cur = 0;
#pragma unroll 1
    for (int k0 = 0; k0 < K; k0 += 16) {
        const bool has_next = (k0 + 16 < K);
        if (has_next) { ldA(k0 + 16); ldB(k0 + 16); }

#pragma unroll
        for (int k = 0; k < 16; k++) {
            float a[TM], bv[TN];
#pragma unroll
            for (int g = 0; g < TM / 4; g++)
                *(float4*)&a[g * 4] = *(const float4*)&As[cur][k][g * 64 + ty * 4];
#pragma unroll
            for (int g = 0; g < TN / 4; g++)
                *(float4*)&bv[g * 4] = *(const float4*)&Bs[cur][k][g * 64 + tx * 4];
#pragma unroll
            for (int i = 0; i < TM; i++)
#pragma unroll
                for (int j = 0; j < TN; j++)
                    acc[i][j] += a[i] * bv[j];
        }

        if (has_next) {
            stA(cur ^ 1); stB(cur ^ 1);
            __syncthreads();
        }
        cur ^= 1;
    }

    if (!SPREPI) {
        float* Cb = C + (long long)b * sC;
#pragma unroll
        for (int i = 0; i < TM; i++) {
            int m = m0 + (i / 4) * 64 + ty * 4 + (i & 3);
#pragma unroll
            for (int gj = 0; gj < TN / 4; gj++) {
                int n = n0 + gj * 64 + tx * 4;
                float4 o;
                o.x = alpha * acc[i][gj * 4 + 0];
                o.y = alpha * acc[i][gj * 4 + 1];
                o.z = alpha * acc[i][gj * 4 + 2];
                o.w = alpha * acc[i][gj * 4 + 3];
                if (Dd) {
                    float4 d = *(const float4*)(Dd + (long long)b * sD + (long long)m * ldd + n);
                    o.x += d.x; o.y += d.y; o.z += d.z; o.w += d.w;
                }
                *(float4*)(Cb + (long long)m * ldc + n) = o;
            }
        }
    } else {
#pragma unroll
        for (int i = 0; i < TM; i++) {
            float s = 0.f;
#pragma unroll
            for (int j = 0; j < TN; j++) s += acc[i][j] * acc[i][j];
            s += __shfl_xor_sync(0xFFFFFFFFu, s, 1);
            s += __shfl_xor_sync(0xFFFFFFFFu, s, 2);
            s += __shfl_xor_sync(0xFFFFFFFFu, s, 4);
            s += __shfl_xor_sync(0xFFFFFFFFu, s, 8);
            if (tx == 0) {
                int m = m0 + (i / 4) * 64 + ty * 4 + (i & 3);
                atomicAdd(&spread[(long long)b * M + m], s);
            }
        }
    }
}

// ======================================================================
// Per-CTA Cholesky (256 threads, 2/row Kahan) + BLOCKED triangular inverse.
// Output: Linv (lower), A^{-1} = Linv^T Linv.
// ======================================================================
#define KADD(s, c, x) { float _y = (x) - (c); float _t = (s) + _y; (c) = (_t - (s)) - _y; (s) = _t; }

#define CHOL_SMEM_BYTES ((2 * 128 * 129 + 3 * 1024 + 128 + 512 + 4) * 4)

__global__ void chol_linv_kernel(const float* __restrict__ in, int ldin, long long strideIn,
                                 float* __restrict__ Lout, int ldout, long long strideOut)
{
    extern __shared__ float sh[];
    float* sL  = sh;                       // [128][129]
    float* sX  = sh + 128 * 129;           // [128][129]
    float* sT  = sh + 2 * 128 * 129;       // [3][32][32] level scratch
    float* rd  = sT + 3 * 1024;            // [128]
    float* pp  = rd + 128;                 // [128][4] partial (s,c) per half
    float* sdi = pp + 512;                 // [1]
#define SL(i,k) sL[(i) * 129 + (k)]
#define SX(i,k) sX[(i) * 129 + (k)]

    const int b   = blockIdx.x;
    const int tid = threadIdx.x;           // 0..255
    const int r   = tid & 127;
    const int h   = tid >> 7;              // half index (0/1)
    const float* A = in + (long long)b * strideIn;
    float* out = Lout + (long long)b * strideOut;

    for (int idx = tid; idx < 128 * 128; idx += 256) {
        int rr = idx >> 7, cc = idx & 127;
        SL(rr, cc) = A[(long long)rr * ldin + cc];
    }
    __syncthreads();

    // ---- phase 1: left-looking Cholesky, 2 threads per row, Kahan ----
    for (int j = 0; j < 128; j++) {
        if (r >= j) {
            float s0 = 0.f, c0 = 0.f, s1 = 0.f, c1 = 0.f;
            for (int k = 2 * h;     k < j; k += 4) KADD(s0, c0, SL(r, k) * SL(j, k));
            for (int k = 2 * h + 1; k < j; k += 4) KADD(s1, c1, SL(r, k) * SL(j, k));
            pp[r * 4 + h * 2]     = s0 + s1;
            pp[r * 4 + h * 2 + 1] = c0 + c1;
        }
        __syncthreads();
        float t = 0.f;
        if (h == 0 && r >= j) {
            float sum = (pp[r * 4] + pp[r * 4 + 2]) + (pp[r * 4 + 1] + pp[r * 4 + 3]);
            t = SL(r, j) - sum;
            if (r == j) {
                float d = sqrtf(t);
                SL(j, j) = d;
                sdi[0] = 1.f / d;
            }
        }
        __syncthreads();
        if (h == 0 && r > j) SL(r, j) = t * sdi[0];
        __syncthreads();
    }

    // ---- phase 2: blocked triangular inverse X = L^{-1} ----
    if (tid < 128) rd[tid] = 1.f / SL(tid, tid);
    for (int idx = tid; idx < 128 * 129; idx += 256) sX[idx] = 0.f;
    __syncthreads();

    // 2a. invert four 32x32 diagonal blocks (128 parallel serial-columns)
    if (tid < 128) {
        int g = tid >> 5, c = tid & 31, base = g * 32;
        int cc = base + c;
        SX(cc, cc) = rd[cc];
        for (int i = c + 1; i < 32; i++) {
            int ri = base + i;
            float s0 = 0.f, c0 = 0.f, s1 = 0.f, c1 = 0.f;
            int k = c;
            for (; k + 1 < i; k += 2) {
                KADD(s0, c0, SL(ri, base + k)     * SX(base + k, cc));
                KADD(s1, c1, SL(ri, base + k + 1) * SX(base + k + 1, cc));
            }
            for (; k < i; k++) KADD(s0, c0, SL(ri, base + k) * SX(base + k, cc));
            SX(ri, cc) = -rd[ri] * ((s0 + s1) + (c0 + c1));
        }
    }
    __syncthreads();

    // 2b. block forward substitution: X_ij = -Dinv_i * (sum_{k=j}^{i-1} L_ik X_kj)
    for (int d = 1; d <= 3; d++) {
        int nb = 4 - d;
        // step A: T_j = sum_k L_{j+d,k} X_{k,j}
        for (int e = tid; e < nb * 1024; e += 256) {
            int blk = e >> 10;
            int rc  = e & 1023;
            int rr  = rc >> 5, cc2 = rc & 31;
            int i   = blk + d;
            int gr  = i * 32 + rr;
            int gc  = blk * 32 + cc2;
            float acc = 0.f;
            for (int kb = blk; kb < i; kb++) {
                int kbase = kb * 32;
#pragma unroll 8
                for (int k = 0; k < 32; k++)
                    acc = fmaf(SL(gr, kbase + k), SX(kbase + k, gc), acc);
            }
            sT[blk * 1024 + rc] = acc;
        }
        __syncthreads();
        // step B: X_{j+d,j} = -Dinv_{j+d} @ T_j
        for (int e = tid; e < nb * 1024; e += 256) {
            int blk = e >> 10;
            int rc  = e & 1023;
            int rr  = rc >> 5, cc2 = rc & 31;
            int i   = blk + d;
            int gr  = i * 32 + rr;
            int gc  = blk * 32 + cc2;
            int ib  = i * 32;
            float acc = 0.f;
#pragma unroll 8
            for (int k = 0; k < 32; k++)
                acc = fmaf(SX(gr, ib + k), sT[blk * 1024 + k * 32 + cc2], acc);
            SX(gr, gc) = -acc;
        }
        __syncthreads();
    }

    for (int idx = tid; idx < 128 * 128; idx += 256) {
        int rr = idx >> 7, cc = idx & 127;
        out[(long long)rr * ldout + cc] = SX(rr, cc);
    }
#undef SL
#undef SX
}

// ---------------- init: W top-right zeros, spread = 1.0, nll acc = 0 ----------------
__global__ void init_kernel(float* __restrict__ W, float* __restrict__ spread, double* acc)
{
    int idx = blockIdx.x * blockDim.x + threadIdx.x;
    if (idx < 128 * 16384) {
        int b  = idx >> 14;
        int ij = idx & 16383;
        int r  = ij >> 7, c = ij & 127;
        W[(long long)b * 65536 + r * 256 + 128 + c] = 0.f;
    }
    if (idx < BB * NQ) spread[idx] = 1.f;
    if (idx == 0) *acc = 0.0;
}

// ---------------- sig zero-fill (side stream) ----------------
__global__ void zerosig_kernel(float4* __restrict__ sig)
{
    long long i = (long long)blockIdx.x * blockDim.x + threadIdx.x;
    const long long NV = SIG_N / 4;
    const long long stride = (long long)gridDim.x * blockDim.x;
    float4 z = make_float4(0.f, 0.f, 0.f, 0.f);
    for (; i < NV; i += stride) sig[i] = z;
}

// ---------------- sig diagonal writer ----------------
__global__ void sigdiag_kernel(float* __restrict__ sig, const float* __restrict__ spread,
                               const float* __restrict__ sig_eps)
{
    int idx = blockIdx.x * blockDim.x + threadIdx.x;
    if (idx >= BB * NQ * DOUT) return;
    int bq = idx >> 6;
    int r  = idx & 63;
    sig[(long long)bq * 4096 + r * 65] = spread[bq] * sig_eps[0];
}

// ---------------- nll ----------------
__global__ void nll_kernel(const float* __restrict__ yq, const float* __restrict__ mu,
                           const float* __restrict__ spread, const float* __restrict__ sig_eps,
                           double* __restrict__ acc)
{
    int bq = blockIdx.x * blockDim.x + threadIdx.x;
    float se = sig_eps[0];
    float sp = spread[bq];
    const float* y = yq + (long long)bq * DOUT;
    const float* m = mu + (long long)bq * DOUT;
    float q = 0.f;
#pragma unroll
    for (int d = 0; d < DOUT; d++) { float r = y[d] - m[d]; q += r * r; }
    float val = (float)DOUT * (logf(sp) + logf(se)) + q / (sp * se);

    __shared__ double s[256];
    s[threadIdx.x] = (double)val;
    __syncthreads();
    for (int o = 128; o; o >>= 1) {
        if (threadIdx.x < o) s[threadIdx.x] += s[threadIdx.x + o];
        __syncthreads();
    }
    if (threadIdx.x == 0) atomicAdd(acc, s[0]);
}

__global__ void nll_final_kernel(const double* __restrict__ acc, float* __restrict__ out)
{
    out[0] = (float)(acc[0] / (double)(BB * NQ));
}

// ---------------- launch ----------------
extern "C" void kernel_launch(void* const* d_in, const int* in_sizes, int n_in,
                              void* d_out, int out_size)
{
    const float* phiS = (const float*)d_in[0];
    const float* yS   = (const float*)d_in[1];
    const float* phiQ = (const float*)d_in[2];
    const float* yQ   = (const float*)d_in[3];
    const float* mpr  = (const float*)d_in[4];
    const float* asym = (const float*)d_in[5];
    const float* se   = (const float*)d_in[6];
    float* out = (float*)d_out;

    float*  buf  = nullptr;
    double* nacc = nullptr;
    cudaGetSymbolAddress((void**)&buf,  g_buf);
    cudaGetSymbolAddress((void**)&nacc, g_nll_acc);

    float* Sp   = buf + OFF_SP;
    float* Mpn  = buf + OFF_MPN;
    float* Sinv = buf + OFF_SINV;
    float* W    = buf + OFF_W;
    float* V    = buf + OFF_V;
    float* X    = buf + OFF_X;
    float* Sc   = buf + OFF_SC;
    float* Rhs  = buf + OFF_RHS;
    float* Tt   = buf + OFF_T;
    float* Mm   = buf + OFF_M;
    float* Spr  = buf + OFF_SPREAD;

    float* mu_out  = out;
    float* sig_out = out + MU_N;
    float* nll_out = out + MU_N + SIG_N;

    static cudaStream_t s2 = nullptr, s3 = nullptr;
    static cudaEvent_t evRoot, evInit, evZero, evSp, evRhs, evWA, evV, evX, evW, evSpr;
    if (!s2) {
        cudaStreamCreateWithFlags(&s2, cudaStreamNonBlocking);
        cudaStreamCreateWithFlags(&s3, cudaStreamNonBlocking);
        cudaEventCreateWithFlags(&evRoot, cudaEventDisableTiming);
        cudaEventCreateWithFlags(&evInit, cudaEventDisableTiming);
        cudaEventCreateWithFlags(&evZero, cudaEventDisableTiming);
        cudaEventCreateWithFlags(&evSp,   cudaEventDisableTiming);
        cudaEventCreateWithFlags(&evRhs,  cudaEventDisableTiming);
        cudaEventCreateWithFlags(&evWA,   cudaEventDisableTiming);
        cudaEventCreateWithFlags(&evV,    cudaEventDisableTiming);
        cudaEventCreateWithFlags(&evX,    cudaEventDisableTiming);
        cudaEventCreateWithFlags(&evW,    cudaEventDisableTiming);
        cudaEventCreateWithFlags(&evSpr,  cudaEventDisableTiming);
        cudaFuncSetAttribute(chol_linv_kernel, cudaFuncAttributeMaxDynamicSharedMemorySize, CHOL_SMEM_BYTES);
    }

    // ---- fork side streams ----
    cudaEventRecord(evRoot, 0);
    cudaStreamWaitEvent(s2, evRoot, 0);
    cudaStreamWaitEvent(s3, evRoot, 0);

    // s2: init + sig zero-fill (DRAM-bound, overlaps FFMA-bound compute)
    init_kernel<<<(128 * 16384 + 255) / 256, 256, 0, s2>>>(W, Spr, nacc);
    cudaEventRecord(evInit, s2);
    zerosig_kernel<<<8192, 256, 0, s2>>>((float4*)sig_out);
    cudaEventRecord(evZero, s2);

    // main: Sp = asym @ asym^T
    gemm_k<128, 128, 0, 1, false><<<dim3(2, 2, 1), 256>>>(256, 256, 256,
        asym, 256, 0,  asym, 256, 0,  nullptr, 0, 0, 1.f,  Sp, 256, 0, nullptr);
    cudaEventRecord(evSp, 0);

    // s3: Mpn = Sp @ m_prior ; Rhs[b] = phiS^T yS + Mpn  (off critical path)
    cudaStreamWaitEvent(s3, evSp, 0);
    gemm_k<128, 64, 0, 0, false><<<dim3(1, 2, 1), 256, 0, s3>>>(256, 64, 256,
        Sp, 256, 0,  mpr, 64, 0,  nullptr, 0, 0, 1.f,  Mpn, 64, 0, nullptr);
    gemm_k<128, 64, 1, 0, false><<<dim3(1, 2, BB), 256, 0, s3>>>(256, 64, 128,
        phiS, 256, 32768,  yS, 64, 8192,  Mpn, 64, 0, 1.f,  Rhs, 64, 16384, nullptr);
    cudaEventRecord(evRhs, s3);

    // main: Sinv[b] = phiS^T phiS + Sp ; chol1 -> WA
    gemm_k<128, 128, 1, 0, false><<<dim3(2, 2, BB), 256>>>(256, 256, 128,
        phiS, 256, 32768,  phiS, 256, 32768,  Sp, 256, 0, 1.f,  Sinv, 256, 65536, nullptr);
    chol_linv_kernel<<<BB, 256, CHOL_SMEM_BYTES>>>(Sinv, 256, 65536, W, 256, 65536);
    cudaEventRecord(evWA, 0);
    // V = WA @ Bblk
    gemm_k<128, 128, 0, 0, false><<<dim3(1, 1, BB), 256>>>(128, 128, 128,
        W, 256, 65536,  Sinv + 128, 256, 65536,  nullptr, 0, 0, 1.f,  V, 128, 16384, nullptr);
    cudaEventRecord(evV, 0);

    // s3: X = WA^T @ V ; then spread1 (needs only WA + init) overlapping chol2
    cudaStreamWaitEvent(s3, evV, 0);
    gemm_k<128, 128, 1, 0, false><<<dim3(1, 1, BB), 256, 0, s3>>>(128, 128, 128,
        W, 256, 65536,  V, 128, 16384,  nullptr, 0, 0, 1.f,  X, 128, 16384, nullptr);
    cudaEventRecord(evX, s3);
    cudaStreamWaitEvent(s3, evInit, 0);
    cudaStreamWaitEvent(s3, evWA, 0);
    gemm_k<128, 128, 0, 1, true><<<dim3(1, 4, BB), 256, 0, s3>>>(512, 128, 128,
        phiQ, 256, 131072,  W, 256, 65536,  nullptr, 0, 0, 1.f,  nullptr, 0, 0, Spr);

    // main: Sc = Dblk - V^T V ; chol2 -> WS ; W_BL = -WS X^T
    gemm_k<128, 128, 1, 0, false><<<dim3(1, 1, BB), 256>>>(128, 128, 128,
        V, 128, 16384,  V, 128, 16384,
        Sinv + 128 * 256 + 128, 256, 65536, -1.f,  Sc, 128, 16384, nullptr);
    chol_linv_kernel<<<BB, 256, CHOL_SMEM_BYTES>>>(Sc, 128, 16384, W + 128 * 256 + 128, 256, 65536);
    cudaStreamWaitEvent(0, evX, 0);
    gemm_k<128, 128, 0, 1, false><<<dim3(1, 1, BB), 256>>>(128, 128, 128,
        W + 128 * 256 + 128, 256, 65536,  X, 128, 16384,
        nullptr, 0, 0, -1.f,  W + 128 * 256, 256, 65536, nullptr);
    cudaStreamWaitEvent(0, evInit, 0);
    cudaEventRecord(evW, 0);

    // s3: spread2 (bottom block rows of W, K=256), overlapping mu chain
    cudaStreamWaitEvent(s3, evW, 0);
    gemm_k<128, 128, 0, 1, true><<<dim3(1, 4, BB), 256, 0, s3>>>(512, 128, 256,
        phiQ, 256, 131072,  W + 128 * 256, 256, 65536,  nullptr, 0, 0, 1.f,  nullptr, 0, 0, Spr);
    cudaEventRecord(evSpr, s3);

    // main: t = W Rhs ; m = W^T t ; mu = phiQ m
    cudaStreamWaitEvent(0, evRhs, 0);
    gemm_k<128, 64, 0, 0, false><<<dim3(1, 2, BB), 256>>>(256, 64, 256,
        W, 256, 65536,  Rhs, 64, 16384,  nullptr, 0, 0, 1.f,  Tt, 64, 16384, nullptr);
    gemm_k<128, 64, 1, 0, false><<<dim3(1, 2, BB), 256>>>(256, 64, 256,
        W, 256, 65536,  Tt, 64, 16384,  nullptr, 0, 0, 1.f,  Mm, 64, 16384, nullptr);
    gemm_k<128, 64, 0, 0, false><<<dim3(1, 4, BB), 256>>>(512, 64, 256,
        phiQ, 256, 131072,  Mm, 64, 16384,  nullptr, 0, 0, 1.f,  mu_out, 64, 32768, nullptr);

    // join
    cudaStreamWaitEvent(0, evSpr, 0);
    cudaStreamWaitEvent(0, evZero, 0);
    nll_kernel<<<(BB * NQ) / 256, 256>>>(yQ, mu_out, Spr, se, nacc);
    sigdiag_kernel<<<(BB * NQ * DOUT + 255) / 256, 256>>>(sig_out, Spr, se);
    nll_final_kernel<<<1, 1>>>(nacc, nll_out);

    (void)in_sizes; (void)n_in; (void)out_size;
}

// round 14
// speedup vs baseline: 1.5518x; 1.5518x over previous
#include <cuda_runtime.h>
#include <math.h>

#define BB   128
#define NS   128
#define NQ   512
#define DIN  256
#define DOUT 64

#define MU_N  ((long long)BB * NQ * DOUT)            // 4,194,304
#define SIG_N ((long long)BB * NQ * DOUT * DOUT)     // 134,217,728

// ---------------- scratch (floats) ----------------
#define OFF_SP     0LL
#define OFF_MPN    65536LL
#define OFF_SINV   81920LL
#define OFF_W      8470528LL
#define OFF_V      16859136LL
#define OFF_X      18956288LL
#define OFF_SC     21053440LL
#define OFF_RHS    23150592LL
#define OFF_T      25247744LL
#define OFF_M      27344896LL
#define OFF_SPREAD 29442048LL
#define BUF_TOTAL  29507584LL

__device__ float  g_buf[BUF_TOTAL];
__device__ double g_nll_acc;

// ======================================================================
// Batched SGEMM, 128x(BN) CTA tile, 256 threads, 8x(BN/16) reg tile,
// double-buffered shared memory.
// ======================================================================
template<int BM, int BN, int TA, int TB, bool SPREPI>
__global__ void __launch_bounds__(256, 2) gemm_k(
    int M, int N, int K,
    const float* __restrict__ A, int lda, long long sA,
    const float* __restrict__ B, int ldb, long long sB,
    const float* __restrict__ Dd, int ldd, long long sD,
    float alpha,
    float* __restrict__ C, int ldc, long long sC,
    float* __restrict__ spread)
{
    constexpr int TM  = BM / 16;
    constexpr int TN  = BN / 16;
    constexpr int LAS = BM + 4;
    constexpr int LBS = BN + 4;
    constexpr int NLA = (BM * 4) / 256;
    constexpr int NLB = (BN * 4) / 256;

    __shared__ float As[2][16][LAS];
    __shared__ float Bs[2][16][LBS];

    const int b  = blockIdx.z;
    const float* Ab = A + (long long)b * sA;
    const float* Bb = B + (long long)b * sB;

    const int m0 = blockIdx.y * BM;
    const int n0 = blockIdx.x * BN;
    const int tid = threadIdx.x;
    const int tx = tid & 15;
    const int ty = tid >> 4;

    float4 ra[NLA], rb[NLB];

    auto ldA = [&](int k0) {
        if constexpr (TA == 0) {
#pragma unroll
            for (int q = 0; q < NLA; q++) {
                int p = tid + q * 256;
                int m = p >> 2, kq = (p & 3) * 4;
                ra[q] = *(const float4*)(Ab + (long long)(m0 + m) * lda + k0 + kq);
            }
        } else {
#pragma unroll
            for (int q = 0; q < NLA; q++) {
                int p = tid + q * 256;
                int k = p / (BM / 4), mq = (p % (BM / 4)) * 4;
                ra[q] = *(const float4*)(Ab + (long long)(k0 + k) * lda + m0 + mq);
            }
        }
    };
    auto stA = [&](int s) {
        if constexpr (TA == 0) {
#pragma unroll
            for (int q = 0; q < NLA; q++) {
                int p = tid + q * 256;
                int m = p >> 2, kq = (p & 3) * 4;
                As[s][kq + 0][m] = ra[q].x; As[s][kq + 1][m] = ra[q].y;
                As[s][kq + 2][m] = ra[q].z; As[s][kq + 3][m] = ra[q].w;
            }
        } else {
#pragma unroll
            for (int q = 0; q < NLA; q++) {
                int p = tid + q * 256;
                int k = p / (BM / 4), mq = (p % (BM / 4)) * 4;
                *(float4*)&As[s][k][mq] = ra[q];
            }
        }
    };
    auto ldB = [&](int k0) {
        if constexpr (TB == 0) {
#pragma unroll
            for (int q = 0; q < NLB; q++) {
                int p = tid + q * 256;
                int k = p / (BN / 4), nq = (p % (BN / 4)) * 4;
                rb[q] = *(const float4*)(Bb + (long long)(k0 + k) * ldb + n0 + nq);
            }
        } else {
#pragma unroll
            for (int q = 0; q < NLB; q++) {
                int p = tid + q * 256;
                int n = p >> 2, kq = (p & 3) * 4;
                rb[q] = *(const float4*)(Bb + (long long)(n0 + n) * ldb + k0 + kq);
            }
        }
    };
    auto stB = [&](int s) {
        if constexpr (TB == 0) {
#pragma unroll
            for (int q = 0; q < NLB; q++) {
                int p = tid + q * 256;
                int k = p / (BN / 4), nq = (p % (BN / 4)) * 4;
                *(float4*)&Bs[s][k][nq] = rb[q];
            }
        } else {
#pragma unroll
            for (int q = 0; q < NLB; q++) {
                int p = tid + q * 256;
                int n = p >> 2, kq = (p & 3) * 4;
                Bs[s][kq + 0][n] = rb[q].x; Bs[s][kq + 1][n] = rb[q].y;
                Bs[s][kq + 2][n] = rb[q].z; Bs[s][kq + 3][n] = rb[q].w;
            }
        }
    };

    float acc[TM][TN];
#pragma unroll
    for (int i = 0; i < TM; i++)
#pragma unroll
        for (int j = 0; j < TN; j++) acc[i][j] = 0.f;

    ldA(0); ldB(0);
    stA(0); stB(0);
    __syncthreads();

    int cur = 0;
#pragma unroll 1
    for (int k0 = 0; k0 < K; k0 += 16) {
        const bool has_next = (k0 + 16 < K);
        if (has_next) { ldA(k0 + 16); ldB(k0 + 16); }

#pragma unroll
        for (int k = 0; k < 16; k++) {
            float a[TM], bv[TN];
#pragma unroll
            for (int g = 0; g < TM / 4; g++)
                *(float4*)&a[g * 4] = *(const float4*)&As[cur][k][g * 64 + ty * 4];
#pragma unroll
            for (int g = 0; g < TN / 4; g++)
                *(float4*)&bv[g * 4] = *(const float4*)&Bs[cur][k][g * 64 + tx * 4];
#pragma unroll
            for (int i = 0; i < TM; i++)
#pragma unroll
                for (int j = 0; j < TN; j++)
                    acc[i][j] += a[i] * bv[j];
        }

        if (has_next) {
            stA(cur ^ 1); stB(cur ^ 1);
            __syncthreads();
        }
        cur ^= 1;
    }

    if (!SPREPI) {
        float* Cb = C + (long long)b * sC;
#pragma unroll
        for (int i = 0; i < TM; i++) {
            int m = m0 + (i / 4) * 64 + ty * 4 + (i & 3);
#pragma unroll
            for (int gj = 0; gj < TN / 4; gj++) {
                int n = n0 + gj * 64 + tx * 4;
                float4 o;
                o.x = alpha * acc[i][gj * 4 + 0];
                o.y = alpha * acc[i][gj * 4 + 1];
                o.z = alpha * acc[i][gj * 4 + 2];
                o.w = alpha * acc[i][gj * 4 + 3];
                if (Dd) {
                    float4 d = *(const float4*)(Dd + (long long)b * sD + (long long)m * ldd + n);
                    o.x += d.x; o.y += d.y; o.z += d.z; o.w += d.w;
                }
                *(float4*)(Cb + (long long)m * ldc + n) = o;
            }
        }
    } else {
#pragma unroll
        for (int i = 0; i < TM; i++) {
            float s = 0.f;
#pragma unroll
            for (int j = 0; j < TN; j++) s += acc[i][j] * acc[i][j];
            s += __shfl_xor_sync(0xFFFFFFFFu, s, 1);
            s += __shfl_xor_sync(0xFFFFFFFFu, s, 2);
            s += __shfl_xor_sync(0xFFFFFFFFu, s, 4);
            s += __shfl_xor_sync(0xFFFFFFFFu, s, 8);
            if (tx == 0) {
                int m = m0 + (i / 4) * 64 + ty * 4 + (i & 3);
                atomicAdd(&spread[(long long)b * M + m], s);
            }
        }
    }
}

// ======================================================================
// Per-CTA Cholesky (256 threads, 2/row Kahan) + BLOCKED triangular inverse.
// Output: Linv (lower), A^{-1} = Linv^T Linv.
// ======================================================================
#define KADD(s, c, x) { float _y = (x) - (c); float _t = (s) + _y; (c) = (_t - (s)) - _y; (s) = _t; }

#define CHOL_SMEM_BYTES ((2 * 128 * 129 + 3 * 1024 + 128 + 512 + 4) * 4)

__global__ void chol_linv_kernel(const float* __restrict__ in, int ldin, long long strideIn,
                                 float* __restrict__ Lout, int ldout, long long strideOut)
{
    extern __shared__ float sh[];
    float* sL  = sh;                       // [128][129]
    float* sX  = sh + 128 * 129;           // [128][129]
    float* sT  = sh + 2 * 128 * 129;       // [3][32][32]
    float* rd  = sT + 3 * 1024;            // [128]
    float* pp  = rd + 128;                 // [128][4]
    float* sdi = pp + 512;                 // [1]
#define SL(i,k) sL[(i) * 129 + (k)]
#define SX(i,k) sX[(i) * 129 + (k)]

    const int b   = blockIdx.x;
    const int tid = threadIdx.x;           // 0..255
    const int r   = tid & 127;
    const int h   = tid >> 7;
    const float* A = in + (long long)b * strideIn;
    float* out = Lout + (long long)b * strideOut;

    for (int idx = tid; idx < 128 * 128; idx += 256) {
        int rr = idx >> 7, cc = idx & 127;
        SL(rr, cc) = A[(long long)rr * ldin + cc];
    }
    __syncthreads();

    // phase 1: left-looking Cholesky, 2 threads per row, Kahan
    for (int j = 0; j < 128; j++) {
        if (r >= j) {
            float s0 = 0.f, c0 = 0.f, s1 = 0.f, c1 = 0.f;
            for (int k = 2 * h;     k < j; k += 4) KADD(s0, c0, SL(r, k) * SL(j, k));
            for (int k = 2 * h + 1; k < j; k += 4) KADD(s1, c1, SL(r, k) * SL(j, k));
            pp[r * 4 + h * 2]     = s0 + s1;
            pp[r * 4 + h * 2 + 1] = c0 + c1;
        }
        __syncthreads();
        float t = 0.f;
        if (h == 0 && r >= j) {
            float sum = (pp[r * 4] + pp[r * 4 + 2]) + (pp[r * 4 + 1] + pp[r * 4 + 3]);
            t = SL(r, j) - sum;
            if (r == j) {
                float d = sqrtf(t);
                SL(j, j) = d;
                sdi[0] = 1.f / d;
            }
        }
        __syncthreads();
        if (h == 0 && r > j) SL(r, j) = t * sdi[0];
        __syncthreads();
    }

    // phase 2: blocked triangular inverse X = L^{-1}
    if (tid < 128) rd[tid] = 1.f / SL(tid, tid);
    for (int idx = tid; idx < 128 * 129; idx += 256) sX[idx] = 0.f;
    __syncthreads();

    // 2a. four 32x32 diagonal blocks, column-serial
    if (tid < 128) {
        int g = tid >> 5, c = tid & 31, base = g * 32;
        int cc = base + c;
        SX(cc, cc) = rd[cc];
        for (int i = c + 1; i < 32; i++) {
            int ri = base + i;
            float s0 = 0.f, c0 = 0.f, s1 = 0.f, c1 = 0.f;
            int k = c;
            for (; k + 1 < i; k += 2) {
                KADD(s0, c0, SL(ri, base + k)     * SX(base + k, cc));
                KADD(s1, c1, SL(ri, base + k + 1) * SX(base + k + 1, cc));
            }
            for (; k < i; k++) KADD(s0, c0, SL(ri, base + k) * SX(base + k, cc));
            SX(ri, cc) = -rd[ri] * ((s0 + s1) + (c0 + c1));
        }
    }
    __syncthreads();

    // 2b. block forward substitution
    for (int d = 1; d <= 3; d++) {
        int nb = 4 - d;
        for (int e = tid; e < nb * 1024; e += 256) {
            int blk = e >> 10;
            int rc  = e & 1023;
            int rr  = rc >> 5, cc2 = rc & 31;
            int i   = blk + d;
            int gr  = i * 32 + rr;
            int gc  = blk * 32 + cc2;
            float acc = 0.f;
            for (int kb = blk; kb < i; kb++) {
                int kbase = kb * 32;
#pragma unroll 8
                for (int k = 0; k < 32; k++)
                    acc = fmaf(SL(gr, kbase + k), SX(kbase + k, gc), acc);
            }
            sT[blk * 1024 + rc] = acc;
        }
        __syncthreads();
        for (int e = tid; e < nb * 1024; e += 256) {
            int blk = e >> 10;
            int rc  = e & 1023;
            int rr  = rc >> 5, cc2 = rc & 31;
            int i   = blk + d;
            int gr  = i * 32 + rr;
            int gc  = blk * 32 + cc2;
            int ib  = i * 32;
            float acc = 0.f;
#pragma unroll 8
            for (int k = 0; k < 32; k++)
                acc = fmaf(SX(gr, ib + k), sT[blk * 1024 + k * 32 + cc2], acc);
            SX(gr, gc) = -acc;
        }
        __syncthreads();
    }

    for (int idx = tid; idx < 128 * 128; idx += 256) {
        int rr = idx >> 7, cc = idx & 127;
        out[(long long)rr * ldout + cc] = SX(rr, cc);
    }
#undef SL
#undef SX
}

// ---------------- init ----------------
__global__ void init_kernel(float* __restrict__ W, float* __restrict__ spread, double* acc)
{
    int idx = blockIdx.x * blockDim.x + threadIdx.x;
    if (idx < 128 * 16384) {
        int b  = idx >> 14;
        int ij = idx & 16383;
        int r  = ij >> 7, c = ij & 127;
        W[(long long)b * 65536 + r * 256 + 128 + c] = 0.f;
    }
    if (idx < BB * NQ) spread[idx] = 1.f;
    if (idx == 0) *acc = 0.0;
}

// ---------------- sig zero-fill (s2) ----------------
__global__ void zerosig_kernel(float4* __restrict__ sig)
{
    long long i = (long long)blockIdx.x * blockDim.x + threadIdx.x;
    const long long NV = SIG_N / 4;
    const long long stride = (long long)gridDim.x * blockDim.x;
    float4 z = make_float4(0.f, 0.f, 0.f, 0.f);
    for (; i < NV; i += stride) sig[i] = z;
}

// ---------------- sig diagonal writer ----------------
__global__ void sigdiag_kernel(float* __restrict__ sig, const float* __restrict__ spread,
                               const float* __restrict__ sig_eps)
{
    int idx = blockIdx.x * blockDim.x + threadIdx.x;
    if (idx >= BB * NQ * DOUT) return;
    int bq = idx >> 6;
    int r  = idx & 63;
    sig[(long long)bq * 4096 + r * 65] = spread[bq] * sig_eps[0];
}

// ---------------- nll ----------------
__global__ void nll_kernel(const float* __restrict__ yq, const float* __restrict__ mu,
                           const float* __restrict__ spread, const float* __restrict__ sig_eps,
                           double* __restrict__ acc)
{
    int bq = blockIdx.x * blockDim.x + threadIdx.x;
    float se = sig_eps[0];
    float sp = spread[bq];
    const float* y = yq + (long long)bq * DOUT;
    const float* m = mu + (long long)bq * DOUT;
    float q = 0.f;
#pragma unroll
    for (int d = 0; d < DOUT; d++) { float r = y[d] - m[d]; q += r * r; }
    float val = (float)DOUT * (logf(sp) + logf(se)) + q / (sp * se);

    __shared__ double s[256];
    s[threadIdx.x] = (double)val;
    __syncthreads();
    for (int o = 128; o; o >>= 1) {
        if (threadIdx.x < o) s[threadIdx.x] += s[threadIdx.x + o];
        __syncthreads();
    }
    if (threadIdx.x == 0) atomicAdd(acc, s[0]);
}

__global__ void nll_final_kernel(const double* __restrict__ acc, float* __restrict__ out)
{
    out[0] = (float)(acc[0] / (double)(BB * NQ));
}

// ---------------- launch ----------------
extern "C" void kernel_launch(void* const* d_in, const int* in_sizes, int n_in,
                              void* d_out, int out_size)
{
    const float* phiS = (const float*)d_in[0];
    const float* yS   = (const float*)d_in[1];
    const float* phiQ = (const float*)d_in[2];
    const float* yQ   = (const float*)d_in[3];
    const float* mpr  = (const float*)d_in[4];
    const float* asym = (const float*)d_in[5];
    const float* se   = (const float*)d_in[6];
    float* out = (float*)d_out;

    float*  buf  = nullptr;
    double* nacc = nullptr;
    cudaGetSymbolAddress((void**)&buf,  g_buf);
    cudaGetSymbolAddress((void**)&nacc, g_nll_acc);

    float* Sp   = buf + OFF_SP;
    float* Mpn  = buf + OFF_MPN;
    float* Sinv = buf + OFF_SINV;
    float* W    = buf + OFF_W;
    float* V    = buf + OFF_V;
    float* X    = buf + OFF_X;
    float* Sc   = buf + OFF_SC;
    float* Rhs  = buf + OFF_RHS;
    float* Tt   = buf + OFF_T;
    float* Mm   = buf + OFF_M;
    float* Spr  = buf + OFF_SPREAD;

    float* mu_out  = out;
    float* sig_out = out + MU_N;
    float* nll_out = out + MU_N + SIG_N;

    static cudaStream_t s2 = nullptr, s3 = nullptr;
    static cudaEvent_t evRoot, evInit, evSp, evRhs, evV, evX, evW, evSpr, evSig;
    if (!s2) {
        cudaStreamCreateWithFlags(&s2, cudaStreamNonBlocking);
        cudaStreamCreateWithFlags(&s3, cudaStreamNonBlocking);
        cudaEventCreateWithFlags(&evRoot, cudaEventDisableTiming);
        cudaEventCreateWithFlags(&evInit, cudaEventDisableTiming);
        cudaEventCreateWithFlags(&evSp,   cudaEventDisableTiming);
        cudaEventCreateWithFlags(&evRhs,  cudaEventDisableTiming);
        cudaEventCreateWithFlags(&evV,    cudaEventDisableTiming);
        cudaEventCreateWithFlags(&evX,    cudaEventDisableTiming);
        cudaEventCreateWithFlags(&evW,    cudaEventDisableTiming);
        cudaEventCreateWithFlags(&evSpr,  cudaEventDisableTiming);
        cudaEventCreateWithFlags(&evSig,  cudaEventDisableTiming);
        cudaFuncSetAttribute(chol_linv_kernel, cudaFuncAttributeMaxDynamicSharedMemorySize, CHOL_SMEM_BYTES);
    }

    // ---- fork ----
    cudaEventRecord(evRoot, 0);
    cudaStreamWaitEvent(s2, evRoot, 0);
    cudaStreamWaitEvent(s3, evRoot, 0);

    // s2: init + sig zero-fill (DRAM-bound; overlaps compute chain)
    init_kernel<<<(128 * 16384 + 255) / 256, 256, 0, s2>>>(W, Spr, nacc);
    cudaEventRecord(evInit, s2);
    zerosig_kernel<<<8192, 256, 0, s2>>>((float4*)sig_out);

    // main: Sp = asym @ asym^T  (8 CTAs for latency)
    gemm_k<128, 64, 0, 1, false><<<dim3(4, 2, 1), 256>>>(256, 256, 256,
        asym, 256, 0,  asym, 256, 0,  nullptr, 0, 0, 1.f,  Sp, 256, 0, nullptr);
    cudaEventRecord(evSp, 0);

    // s3: Mpn = Sp @ m_prior ; Rhs = phiS^T yS + Mpn  (off critical path)
    cudaStreamWaitEvent(s3, evSp, 0);
    gemm_k<128, 64, 0, 0, false><<<dim3(1, 2, 1), 256, 0, s3>>>(256, 64, 256,
        Sp, 256, 0,  mpr, 64, 0,  nullptr, 0, 0, 1.f,  Mpn, 64, 0, nullptr);
    gemm_k<128, 64, 1, 0, false><<<dim3(1, 2, BB), 256, 0, s3>>>(256, 64, 128,
        phiS, 256, 32768,  yS, 64, 8192,  Mpn, 64, 0, 1.f,  Rhs, 64, 16384, nullptr);
    cudaEventRecord(evRhs, s3);

    // main: Sinv = phiS^T phiS + Sp ; chol1 -> WA ; V = WA @ B
    gemm_k<128, 128, 1, 0, false><<<dim3(2, 2, BB), 256>>>(256, 256, 128,
        phiS, 256, 32768,  phiS, 256, 32768,  Sp, 256, 0, 1.f,  Sinv, 256, 65536, nullptr);
    chol_linv_kernel<<<BB, 256, CHOL_SMEM_BYTES>>>(Sinv, 256, 65536, W, 256, 65536);
    gemm_k<128, 128, 0, 0, false><<<dim3(1, 1, BB), 256>>>(128, 128, 128,
        W, 256, 65536,  Sinv + 128, 256, 65536,  nullptr, 0, 0, 1.f,  V, 128, 16384, nullptr);
    cudaEventRecord(evV, 0);

    // s3: X = WA^T @ V  (concurrent with Sc + chol2)
    cudaStreamWaitEvent(s3, evV, 0);
    gemm_k<128, 128, 1, 0, false><<<dim3(1, 1, BB), 256, 0, s3>>>(128, 128, 128,
        W, 256, 65536,  V, 128, 16384,  nullptr, 0, 0, 1.f,  X, 128, 16384, nullptr);
    cudaEventRecord(evX, s3);

    // main: Sc = D - V^T V ; chol2 -> WS ; W_BL = -WS X^T
    gemm_k<128, 128, 1, 0, false><<<dim3(1, 1, BB), 256>>>(128, 128, 128,
        V, 128, 16384,  V, 128, 16384,
        Sinv + 128 * 256 + 128, 256, 65536, -1.f,  Sc, 128, 16384, nullptr);
    chol_linv_kernel<<<BB, 256, CHOL_SMEM_BYTES>>>(Sc, 128, 16384, W + 128 * 256 + 128, 256, 65536);
    cudaStreamWaitEvent(0, evX, 0);
    gemm_k<128, 128, 0, 1, false><<<dim3(1, 1, BB), 256>>>(128, 128, 128,
        W + 128 * 256 + 128, 256, 65536,  X, 128, 16384,
        nullptr, 0, 0, -1.f,  W + 128 * 256, 256, 65536, nullptr);
    cudaStreamWaitEvent(0, evInit, 0);
    cudaEventRecord(evW, 0);

    // s3: spread (both halves) AFTER evW — overlaps main's Tt/Mm/mu tail only
    cudaStreamWaitEvent(s3, evW, 0);
    gemm_k<128, 128, 0, 1, true><<<dim3(1, 4, BB), 256, 0, s3>>>(512, 128, 128,
        phiQ, 256, 131072,  W, 256, 65536,  nullptr, 0, 0, 1.f,  nullptr, 0, 0, Spr);
    gemm_k<128, 128, 0, 1, true><<<dim3(1, 4, BB), 256, 0, s3>>>(512, 128, 256,
        phiQ, 256, 131072,  W + 128 * 256, 256, 65536,  nullptr, 0, 0, 1.f,  nullptr, 0, 0, Spr);
    cudaEventRecord(evSpr, s3);

    // main: t = W Rhs ; m = W^T t ; mu = phiQ m
    cudaStreamWaitEvent(0, evRhs, 0);
    gemm_k<128, 64, 0, 0, false><<<dim3(1, 2, BB), 256>>>(256, 64, 256,
        W, 256, 65536,  Rhs, 64, 16384,  nullptr, 0, 0, 1.f,  Tt, 64, 16384, nullptr);
    gemm_k<128, 64, 1, 0, false><<<dim3(1, 2, BB), 256>>>(256, 64, 256,
        W, 256, 65536,  Tt, 64, 16384,  nullptr, 0, 0, 1.f,  Mm, 64, 16384, nullptr);
    gemm_k<128, 64, 0, 0, false><<<dim3(1, 4, BB), 256>>>(512, 64, 256,
        phiQ, 256, 131072,  Mm, 64, 16384,  nullptr, 0, 0, 1.f,  mu_out, 64, 32768, nullptr);

    // s2: sigdiag (after zerosig in-order; needs spread)
    cudaStreamWaitEvent(s2, evSpr, 0);
    sigdiag_kernel<<<(BB * NQ * DOUT + 255) / 256, 256, 0, s2>>>(sig_out, Spr, se);
    cudaEventRecord(evSig, s2);

    // main: nll (needs mu in-order + spread), then final join
    cudaStreamWaitEvent(0, evSpr, 0);
    nll_kernel<<<(BB * NQ) / 256, 256>>>(yQ, mu_out, Spr, se, nacc);
    cudaStreamWaitEvent(0, evSig, 0);
    nll_final_kernel<<<1, 1>>>(nacc, nll_out);

    (void)in_sizes; (void)n_in; (void)out_size;
}